// round 1
// baseline (speedup 1.0000x reference)
#include <cuda_runtime.h>
#include <math.h>

// ---------------------------------------------------------------------------
// Problem constants
// ---------------------------------------------------------------------------
constexpr int NB  = 8;     // batch
constexpr int LT  = 512;   // tgt len
constexpr int LS  = 512;   // src len
constexpr int D   = 512;   // d_model
constexpr int H   = 8;     // heads
constexpr int DK  = 64;    // d_k
constexpr int DV  = 64;    // d_v
constexpr int DI  = 2048;  // ffn inner
constexpr int NL  = 6;     // layers
constexpr int T   = NB * LT;               // 4096 tokens

constexpr long long X_SIZE  = (long long)T * D;                 // 2,097,152
constexpr long long ATT     = (long long)H * NB * LT * LT;      // 16,777,216
constexpr long long SLF_OFF = X_SIZE;
constexpr long long ENC_OFF = X_SIZE + (long long)NL * ATT;

// ---------------------------------------------------------------------------
// Scratch (no allocation allowed -> __device__ globals)
// ---------------------------------------------------------------------------
__device__ float g_x  [T * D];       // activations
__device__ float g_q  [H * T * DK];  // per-head Q
__device__ float g_k  [H * T * DK];  // per-head K
__device__ float g_v  [H * T * DK];  // per-head V
__device__ float g_ctx[T * D];       // attn context / ffn out
__device__ float g_h  [T * DI];      // ffn hidden / proj temp

// ---------------------------------------------------------------------------
// Generic tiled fp32 GEMM: C = alpha * A(MxK) * op(B)(KxN) (+bias) (+relu)
// Tiles: BM=128, BN=64, BK=16; 256 threads; 8x4 per thread.
// Batched over blockIdx.z with a 2-level (zo, zi) stride decomposition so one
// kernel covers per-head, per-(head,batch) and interleaved output layouts.
// All M%128 == N%64 == K%16 == 0 for every call site (checked statically).
// ---------------------------------------------------------------------------
__global__ __launch_bounds__(256) void gemm_kernel(
    const float* __restrict__ A, int lda, long long sAo, long long sAi,
    const float* __restrict__ Bm, int ldb, long long sBo, long long sBi,
    float* __restrict__ C, int ldc, long long sCo, long long sCi,
    int M, int N, int K, int zdiv,
    float alpha, const float* __restrict__ bias, int relu, int transB)
{
    __shared__ float As[16][128];
    __shared__ float Bs[16][64];

    const int zo = blockIdx.z / zdiv;
    const int zi = blockIdx.z % zdiv;
    A  += (long long)zo * sAo + (long long)zi * sAi;
    Bm += (long long)zo * sBo + (long long)zi * sBi;
    C  += (long long)zo * sCo + (long long)zi * sCi;

    const int m0 = blockIdx.y * 128;
    const int n0 = blockIdx.x * 64;
    const int tid = threadIdx.x;
    const int ty = tid >> 4;   // 0..15 -> row group of 8
    const int tx = tid & 15;   // 0..15 -> col group of 4

    float acc[8][4];
#pragma unroll
    for (int i = 0; i < 8; i++)
#pragma unroll
        for (int j = 0; j < 4; j++) acc[i][j] = 0.0f;

    const int ar  = tid >> 2;        // 0..63
    const int akv = (tid & 3) * 4;   // 0,4,8,12

    for (int k0 = 0; k0 < K; k0 += 16) {
        // --- load A tile (128 x 16), store transposed As[k][row]
#pragma unroll
        for (int rr = 0; rr < 128; rr += 64) {
            const float4 av = *reinterpret_cast<const float4*>(
                A + (size_t)(m0 + ar + rr) * lda + k0 + akv);
            As[akv + 0][ar + rr] = av.x;
            As[akv + 1][ar + rr] = av.y;
            As[akv + 2][ar + rr] = av.z;
            As[akv + 3][ar + rr] = av.w;
        }
        // --- load B tile (16 x 64)
        if (!transB) {
            const int kr = tid >> 4;
            const int nv = (tid & 15) * 4;
            const float4 bv = *reinterpret_cast<const float4*>(
                Bm + (size_t)(k0 + kr) * ldb + n0 + nv);
            *reinterpret_cast<float4*>(&Bs[kr][nv]) = bv;
        } else {
            const int nr = tid >> 2;         // 0..63
            const int kv = (tid & 3) * 4;
            const float4 bv = *reinterpret_cast<const float4*>(
                Bm + (size_t)(n0 + nr) * ldb + k0 + kv);
            Bs[kv + 0][nr] = bv.x;
            Bs[kv + 1][nr] = bv.y;
            Bs[kv + 2][nr] = bv.z;
            Bs[kv + 3][nr] = bv.w;
        }
        __syncthreads();

#pragma unroll
        for (int k = 0; k < 16; k++) {
            const float4 a0 = *reinterpret_cast<const float4*>(&As[k][ty * 8]);
            const float4 a1 = *reinterpret_cast<const float4*>(&As[k][ty * 8 + 4]);
            const float4 bv = *reinterpret_cast<const float4*>(&Bs[k][tx * 4]);
            const float a[8] = {a0.x, a0.y, a0.z, a0.w, a1.x, a1.y, a1.z, a1.w};
            const float b[4] = {bv.x, bv.y, bv.z, bv.w};
#pragma unroll
            for (int i = 0; i < 8; i++)
#pragma unroll
                for (int j = 0; j < 4; j++) acc[i][j] += a[i] * b[j];
        }
        __syncthreads();
    }

    float bfrag[4] = {0.f, 0.f, 0.f, 0.f};
    if (bias) {
#pragma unroll
        for (int j = 0; j < 4; j++) bfrag[j] = bias[n0 + tx * 4 + j];
    }
#pragma unroll
    for (int i = 0; i < 8; i++) {
        const int row = m0 + ty * 8 + i;
        float4 cv;
        cv.x = acc[i][0] * alpha + bfrag[0];
        cv.y = acc[i][1] * alpha + bfrag[1];
        cv.z = acc[i][2] * alpha + bfrag[2];
        cv.w = acc[i][3] * alpha + bfrag[3];
        if (relu) {
            cv.x = fmaxf(cv.x, 0.f); cv.y = fmaxf(cv.y, 0.f);
            cv.z = fmaxf(cv.z, 0.f); cv.w = fmaxf(cv.w, 0.f);
        }
        *reinterpret_cast<float4*>(C + (size_t)row * ldc + n0 + tx * 4) = cv;
    }
}

// ---------------------------------------------------------------------------
// In-place masked softmax over rows of length 512.
// grid = (LT, H*NB); causal flag adds the s>q triangular mask.
// Pad mask: seq[b*512 + s] == 0 -> -inf.
// ---------------------------------------------------------------------------
__global__ void softmax_kernel(float* __restrict__ attn,
                               const int* __restrict__ seq, int causal)
{
    const int q  = blockIdx.x;
    const int hb = blockIdx.y;
    const int b  = hb % NB;
    float* row = attn + ((size_t)hb * LT + q) * (size_t)LT;
    const int tid = threadIdx.x;
    const int s0 = tid, s1 = tid + 256;

    float v0 = row[s0];
    float v1 = row[s1];
    if ((causal && s0 > q) || seq[b * LS + s0] == 0) v0 = -INFINITY;
    if ((causal && s1 > q) || seq[b * LS + s1] == 0) v1 = -INFINITY;

    __shared__ float red[256];
    red[tid] = fmaxf(v0, v1);
    __syncthreads();
    for (int off = 128; off > 0; off >>= 1) {
        if (tid < off) red[tid] = fmaxf(red[tid], red[tid + off]);
        __syncthreads();
    }
    const float m = red[0];
    __syncthreads();

    const float e0 = expf(v0 - m);   // expf(-inf) = 0
    const float e1 = expf(v1 - m);
    red[tid] = e0 + e1;
    __syncthreads();
    for (int off = 128; off > 0; off >>= 1) {
        if (tid < off) red[tid] += red[tid + off];
        __syncthreads();
    }
    const float inv = 1.0f / red[0];
    row[s0] = e0 * inv;
    row[s1] = e1 * inv;
}

// ---------------------------------------------------------------------------
// xout = LayerNorm(y + res) * g + b   (row length 512, one block per row)
// xout may alias res (all reads happen before writes within the block).
// ---------------------------------------------------------------------------
__global__ void add_ln_kernel(const float* __restrict__ y,
                              const float* __restrict__ res,
                              float* __restrict__ xout,
                              const float* __restrict__ g,
                              const float* __restrict__ b)
{
    const int t = blockIdx.x;
    const int tid = threadIdx.x;
    const float* yr = y   + (size_t)t * D;
    const float* rr = res + (size_t)t * D;

    const float v0 = yr[tid] + rr[tid];
    const float v1 = yr[tid + 256] + rr[tid + 256];

    __shared__ float red[256];
    red[tid] = v0 + v1;
    __syncthreads();
    for (int off = 128; off > 0; off >>= 1) {
        if (tid < off) red[tid] += red[tid + off];
        __syncthreads();
    }
    const float mu = red[0] * (1.0f / 512.0f);
    __syncthreads();

    const float d0 = v0 - mu;
    const float d1 = v1 - mu;
    red[tid] = d0 * d0 + d1 * d1;
    __syncthreads();
    for (int off = 128; off > 0; off >>= 1) {
        if (tid < off) red[tid] += red[tid + off];
        __syncthreads();
    }
    const float var = red[0] * (1.0f / 512.0f);
    const float sc = rsqrtf(var + 1e-5f);

    xout[(size_t)t * D + tid]       = d0 * sc * g[tid]       + b[tid];
    xout[(size_t)t * D + tid + 256] = d1 * sc * g[tid + 256] + b[tid + 256];
}

// ---------------------------------------------------------------------------
// x[t] = tgt_emb[tgt_seq[t]] + pos_emb[tgt_pos[t]]
// ---------------------------------------------------------------------------
__global__ void embed_kernel(const int* __restrict__ seq,
                             const int* __restrict__ pos,
                             const float* __restrict__ wemb,
                             const float* __restrict__ pemb,
                             float* __restrict__ x)
{
    const int t = blockIdx.x;
    const int tid = threadIdx.x;
    const size_t wo = (size_t)seq[t] * D;
    const size_t po = (size_t)pos[t] * D;
    x[(size_t)t * D + tid]       = wemb[wo + tid]       + pemb[po + tid];
    x[(size_t)t * D + tid + 256] = wemb[wo + tid + 256] + pemb[po + tid + 256];
}

__global__ void copy_kernel(const float* __restrict__ s, float* __restrict__ d,
                            long long n)
{
    long long i = (long long)blockIdx.x * blockDim.x + threadIdx.x;
    const long long stride = (long long)gridDim.x * blockDim.x;
    for (; i < n; i += stride) d[i] = s[i];
}

// ---------------------------------------------------------------------------
// Host-side launch helper
// ---------------------------------------------------------------------------
static inline void gemm(const float* A, int lda, long long sAo, long long sAi,
                        const float* Bm, int ldb, long long sBo, long long sBi,
                        float* C, int ldc, long long sCo, long long sCi,
                        int M, int N, int K, int Z, int zdiv,
                        float alpha, const float* bias, int relu, int transB)
{
    dim3 grid(N / 64, M / 128, Z);
    gemm_kernel<<<grid, 256>>>(A, lda, sAo, sAi, Bm, ldb, sBo, sBi,
                               C, ldc, sCo, sCi, M, N, K, zdiv,
                               alpha, bias, relu, transB);
}

extern "C" void kernel_launch(void* const* d_in, const int* in_sizes, int n_in,
                              void* d_out, int out_size)
{
    const int*   tgt_seq    = (const int*)  d_in[0];
    const int*   tgt_pos    = (const int*)  d_in[1];
    const int*   src_seq    = (const int*)  d_in[2];
    const float* enc_output = (const float*)d_in[3];
    const float* tgt_emb    = (const float*)d_in[4];
    const float* pos_emb    = (const float*)d_in[5];
    const float* slf_wq     = (const float*)d_in[6];
    const float* slf_wk     = (const float*)d_in[7];
    const float* slf_wv     = (const float*)d_in[8];
    const float* slf_pw     = (const float*)d_in[9];
    const float* slf_pb     = (const float*)d_in[10];
    const float* slf_g      = (const float*)d_in[11];
    const float* slf_b      = (const float*)d_in[12];
    const float* enc_wq     = (const float*)d_in[13];
    const float* enc_wk     = (const float*)d_in[14];
    const float* enc_wv     = (const float*)d_in[15];
    const float* enc_wv_b   = nullptr; (void)enc_wv_b;
    const float* enc_pw     = (const float*)d_in[16];
    const float* enc_pb     = (const float*)d_in[17];
    const float* enc_g      = (const float*)d_in[18];
    const float* enc_b      = (const float*)d_in[19];
    const float* ffn_w1     = (const float*)d_in[20];
    const float* ffn_b1     = (const float*)d_in[21];
    const float* ffn_w2     = (const float*)d_in[22];
    const float* ffn_b2     = (const float*)d_in[23];
    const float* ffn_g      = (const float*)d_in[24];
    const float* ffn_b      = (const float*)d_in[25];

    float* out = (float*)d_out;

    float *x, *q, *k, *v, *ctx, *hbuf;
    cudaGetSymbolAddress((void**)&x,    g_x);
    cudaGetSymbolAddress((void**)&q,    g_q);
    cudaGetSymbolAddress((void**)&k,    g_k);
    cudaGetSymbolAddress((void**)&v,    g_v);
    cudaGetSymbolAddress((void**)&ctx,  g_ctx);
    cudaGetSymbolAddress((void**)&hbuf, g_h);

    const float scale = 1.0f / sqrtf((float)D);

    const long long HW   = (long long)H * D * DK;   // per-layer head-weight block
    const long long sHT  = (long long)T * DK;       // head stride in q/k/v
    const long long sBT  = (long long)LT * DK;      // batch stride in q/k/v
    const long long sAh  = (long long)NB * LT * LT; // head stride in attn
    const long long sAb  = (long long)LT * LT;      // batch stride in attn

    embed_kernel<<<T, 256>>>(tgt_seq, tgt_pos, tgt_emb, pos_emb, x);

    for (int l = 0; l < NL; l++) {
        // ================= self-attention =================
        gemm(x, D, 0, 0, slf_wq + (long long)l * HW, DK, (long long)D * DK, 0,
             q, DK, sHT, 0, T, DK, D, H, 1, 1.f, nullptr, 0, 0);
        gemm(x, D, 0, 0, slf_wk + (long long)l * HW, DK, (long long)D * DK, 0,
             k, DK, sHT, 0, T, DK, D, H, 1, 1.f, nullptr, 0, 0);
        gemm(x, D, 0, 0, slf_wv + (long long)l * HW, DK, (long long)D * DK, 0,
             v, DK, sHT, 0, T, DK, D, H, 1, 1.f, nullptr, 0, 0);

        float* attn = out + SLF_OFF + (long long)l * ATT;
        gemm(q, DK, sHT, sBT, k, DK, sHT, sBT,
             attn, LT, sAh, sAb, LT, LT, DK, H * NB, NB,
             scale, nullptr, 0, /*transB=*/1);
        softmax_kernel<<<dim3(LT, H * NB), 256>>>(attn, tgt_seq, /*causal=*/1);
        gemm(attn, LT, sAh, sAb, v, DK, sHT, sBT,
             ctx, H * DV, DV, (long long)LT * H * DV, LT, DK, LT, H * NB, NB,
             1.f, nullptr, 0, 0);
        gemm(ctx, D, 0, 0, slf_pw + (long long)l * D * D, D, 0, 0,
             hbuf, D, 0, 0, T, D, D, 1, 1, 1.f, slf_pb + (long long)l * D, 0, 0);
        add_ln_kernel<<<T, 256>>>(hbuf, x, x, slf_g + (long long)l * D,
                                  slf_b + (long long)l * D);

        // ================= cross-attention =================
        gemm(x, D, 0, 0, enc_wq + (long long)l * HW, DK, (long long)D * DK, 0,
             q, DK, sHT, 0, T, DK, D, H, 1, 1.f, nullptr, 0, 0);
        gemm(enc_output, D, 0, 0, enc_wk + (long long)l * HW, DK, (long long)D * DK, 0,
             k, DK, sHT, 0, T, DK, D, H, 1, 1.f, nullptr, 0, 0);
        gemm(enc_output, D, 0, 0, enc_wv + (long long)l * HW, DK, (long long)D * DK, 0,
             v, DK, sHT, 0, T, DK, D, H, 1, 1.f, nullptr, 0, 0);

        float* eattn = out + ENC_OFF + (long long)l * ATT;
        gemm(q, DK, sHT, sBT, k, DK, sHT, sBT,
             eattn, LS, sAh, sAb, LT, LS, DK, H * NB, NB,
             scale, nullptr, 0, /*transB=*/1);
        softmax_kernel<<<dim3(LT, H * NB), 256>>>(eattn, src_seq, /*causal=*/0);
        gemm(eattn, LS, sAh, sAb, v, DK, sHT, sBT,
             ctx, H * DV, DV, (long long)LT * H * DV, LT, DK, LS, H * NB, NB,
             1.f, nullptr, 0, 0);
        gemm(ctx, D, 0, 0, enc_pw + (long long)l * D * D, D, 0, 0,
             hbuf, D, 0, 0, T, D, D, 1, 1, 1.f, enc_pb + (long long)l * D, 0, 0);
        add_ln_kernel<<<T, 256>>>(hbuf, x, x, enc_g + (long long)l * D,
                                  enc_b + (long long)l * D);

        // ================= feed-forward =================
        gemm(x, D, 0, 0, ffn_w1 + (long long)l * D * DI, DI, 0, 0,
             hbuf, DI, 0, 0, T, DI, D, 1, 1, 1.f,
             ffn_b1 + (long long)l * DI, /*relu=*/1, 0);
        gemm(hbuf, DI, 0, 0, ffn_w2 + (long long)l * DI * D, D, 0, 0,
             ctx, D, 0, 0, T, D, DI, 1, 1, 1.f,
             ffn_b2 + (long long)l * D, 0, 0);
        add_ln_kernel<<<T, 256>>>(ctx, x, x, ffn_g + (long long)l * D,
                                  ffn_b + (long long)l * D);
    }

    copy_kernel<<<2048, 256>>>(x, out, X_SIZE);
}